// round 8
// baseline (speedup 1.0000x reference)
#include <cuda_runtime.h>
#include <cuda_bf16.h>
#include <cstdint>

#define BB 16384
#define FF 50
#define EE 64

// Stage-1 intermediate h_out [B,F,E], fp32 (~210MB).
__device__ float g_ho[(size_t)BB * FF * EE];

// ======================= helpers =======================
__device__ __forceinline__ uint32_t smem_u32(const void* p) {
    uint32_t a;
    asm("{ .reg .u64 t; cvta.to.shared.u64 t, %1; cvt.u32.u64 %0, t; }"
        : "=r"(a) : "l"(p));
    return a;
}
__device__ __forceinline__ void ldsm4(uint32_t* r, uint32_t a) {
    asm volatile("ldmatrix.sync.aligned.m8n8.x4.shared.b16 {%0,%1,%2,%3}, [%4];"
        : "=r"(r[0]), "=r"(r[1]), "=r"(r[2]), "=r"(r[3]) : "r"(a));
}
__device__ __forceinline__ void ldsm4t(uint32_t* r, uint32_t a) {
    asm volatile("ldmatrix.sync.aligned.m8n8.x4.trans.shared.b16 {%0,%1,%2,%3}, [%4];"
        : "=r"(r[0]), "=r"(r[1]), "=r"(r[2]), "=r"(r[3]) : "r"(a));
}
__device__ __forceinline__ void mma16816(float* d, const uint32_t* a,
                                         uint32_t b0, uint32_t b1) {
    asm volatile(
        "mma.sync.aligned.m16n8k16.row.col.f32.bf16.bf16.f32 "
        "{%0,%1,%2,%3}, {%4,%5,%6,%7}, {%8,%9}, {%0,%1,%2,%3};"
        : "+f"(d[0]), "+f"(d[1]), "+f"(d[2]), "+f"(d[3])
        : "r"(a[0]), "r"(a[1]), "r"(a[2]), "r"(a[3]), "r"(b0), "r"(b1));
}

// Convert float4 -> bf16 hi/lo, store into [row][64]bf16 tile (128B rows,
// XOR-(row&7)<<4 permuted so ldmatrix over 8 consecutive rows is conflict-free).
__device__ __forceinline__ void split_store4(char* hiB, char* loB, int row, int c4,
                                             float4 v) {
    __nv_bfloat16 h0 = __float2bfloat16_rn(v.x);
    __nv_bfloat16 h1 = __float2bfloat16_rn(v.y);
    __nv_bfloat16 h2 = __float2bfloat16_rn(v.z);
    __nv_bfloat16 h3 = __float2bfloat16_rn(v.w);
    __nv_bfloat16 l0 = __float2bfloat16_rn(v.x - __bfloat162float(h0));
    __nv_bfloat16 l1 = __float2bfloat16_rn(v.y - __bfloat162float(h1));
    __nv_bfloat16 l2 = __float2bfloat16_rn(v.z - __bfloat162float(h2));
    __nv_bfloat16 l3 = __float2bfloat16_rn(v.w - __bfloat162float(h3));
    __nv_bfloat162 hp0 = __nv_bfloat162(h0, h1), hp1 = __nv_bfloat162(h2, h3);
    __nv_bfloat162 lp0 = __nv_bfloat162(l0, l1), lp1 = __nv_bfloat162(l2, l3);
    uint32_t byte0 = (uint32_t)(row * 128 + c4 * 8);
    uint32_t sw = byte0 ^ (((uint32_t)row & 7u) << 4);
    *reinterpret_cast<uint32_t*>(hiB + sw)     = *reinterpret_cast<uint32_t*>(&hp0);
    *reinterpret_cast<uint32_t*>(hiB + sw + 4) = *reinterpret_cast<uint32_t*>(&hp1);
    *reinterpret_cast<uint32_t*>(loB + sw)     = *reinterpret_cast<uint32_t*>(&lp0);
    *reinterpret_cast<uint32_t*>(loB + sw + 4) = *reinterpret_cast<uint32_t*>(&lp1);
}

// ============================================================================
// Stage 1 / Stage 3: per-field GEMM via mma.sync bf16-split.
//   Y[b,i] = sum_j X[b,j] * W[f,i,j]   (+bias if ADD_BIAS)
// Grid (B/128, F), 128 threads (4 warps). CTA tile 128b x 64i, K=64.
// fp32 output, epilogue staged through smem for coalesced 256B-row stores.
// ADD_BIAS variant runs IN-PLACE on d_out.
// ============================================================================
#define GX_HI 0
#define GX_LO 16384
#define GW_HI 32768
#define GW_LO 40960
#define G_BIAS 49152
#define G_SMEM 49664

template <bool ADD_BIAS>
__global__ __launch_bounds__(128, 4) void field_gemm_mma(
    const float* __restrict__ X, const float* __restrict__ W,
    const float* __restrict__ bias, float* __restrict__ Yf) {
    extern __shared__ char smem[];
    const uint32_t sb = smem_u32(smem);
    const int tid = threadIdx.x, w = tid >> 5, l = tid & 31;
    const int f = blockIdx.y, b0 = blockIdx.x * 128;

    if (ADD_BIAS && tid < 16)
        reinterpret_cast<float4*>(smem + G_BIAS)[tid] =
            reinterpret_cast<const float4*>(bias)[tid];

    // Stage X tile (128 x 64 fp32) -> bf16 hi/lo
    const float* Xb = X + (size_t)b0 * (FF * EE) + (size_t)f * EE;
#pragma unroll
    for (int t = 0; t < 16; t++) {
        int idx = tid + t * 128;
        int b = idx >> 4, c4 = idx & 15;
        float4 v = *reinterpret_cast<const float4*>(Xb + (size_t)b * (FF * EE) + c4 * 4);
        split_store4(smem + GX_HI, smem + GX_LO, b, c4, v);
    }
    // Stage W[f] (64 x 64): rows are n=i, k=j contiguous
    const float* Wf = W + (size_t)f * EE * EE;
#pragma unroll
    for (int t = 0; t < 8; t++) {
        int idx = tid + t * 128;
        int n = idx >> 4, c4 = idx & 15;
        float4 v = *reinterpret_cast<const float4*>(Wf + n * EE + c4 * 4);
        split_store4(smem + GW_HI, smem + GW_LO, n, c4, v);
    }
    __syncthreads();

    const int arow0 = w * 32 + (l & 15);
    const int achk  = l >> 4;
    const int brow  = (l & 7) + ((l >> 4) << 3);
    const int bchk  = (l >> 3) & 1;

    float D[2][8][4] = {};

#pragma unroll
    for (int ks = 0; ks < 4; ks++) {
        uint32_t Ahi[2][4], Alo[2][4];
#pragma unroll
        for (int mt = 0; mt < 2; mt++) {
            int row = arow0 + mt * 16;
            uint32_t off = (uint32_t)(row * 128) +
                           ((uint32_t)((2 * ks + achk) ^ (row & 7)) << 4);
            ldsm4(Ahi[mt], sb + GX_HI + off);
            ldsm4(Alo[mt], sb + GX_LO + off);
        }
#pragma unroll
        for (int p = 0; p < 4; p++) {
            int nrow = p * 16 + brow;
            uint32_t off = (uint32_t)(nrow * 128) +
                           ((uint32_t)((2 * ks + bchk) ^ (nrow & 7)) << 4);
            uint32_t Bhi[4], Blo[4];
            ldsm4(Bhi, sb + GW_HI + off);
            ldsm4(Blo, sb + GW_LO + off);
#pragma unroll
            for (int mt = 0; mt < 2; mt++) {
                mma16816(D[mt][2 * p],     Ahi[mt], Bhi[0], Bhi[1]);
                mma16816(D[mt][2 * p],     Ahi[mt], Blo[0], Blo[1]);
                mma16816(D[mt][2 * p],     Alo[mt], Bhi[0], Bhi[1]);
                mma16816(D[mt][2 * p + 1], Ahi[mt], Bhi[2], Bhi[3]);
                mma16816(D[mt][2 * p + 1], Ahi[mt], Blo[2], Blo[3]);
                mma16816(D[mt][2 * p + 1], Alo[mt], Bhi[2], Bhi[3]);
            }
        }
    }

    // -------- epilogue: stage fp32 through smem, coalesced 256B-row stores --
    __syncthreads();   // done reading X/W smem; reuse [0, 32KB)

    const int r0 = l >> 2, c0 = (l & 3) * 2;
#pragma unroll
    for (int mt = 0; mt < 2; mt++)
#pragma unroll
        for (int half = 0; half < 2; half++) {
            int rl = w * 32 + mt * 16 + half * 8 + r0;
            uint32_t rsw = ((uint32_t)rl & 7u) << 4;
#pragma unroll
            for (int nt = 0; nt < 8; nt++) {
                float2 v = make_float2(D[mt][nt][2 * half], D[mt][nt][2 * half + 1]);
                uint32_t off = (uint32_t)(rl * 256) +
                               (((uint32_t)((nt * 8 + c0) * 4)) ^ rsw);
                *reinterpret_cast<float2*>(smem + off) = v;
            }
        }
    __syncthreads();
    const float* bsm = reinterpret_cast<const float*>(smem + G_BIAS);
#pragma unroll
    for (int it = 0; it < 16; it++) {
        int rl = w * 32 + it * 2 + (l >> 4);
        int u  = l & 15;
        uint32_t off = (uint32_t)(rl * 256) +
                       (((uint32_t)(u * 16)) ^ (((uint32_t)rl & 7u) << 4));
        float4 v = *reinterpret_cast<const float4*>(smem + off);
        if (ADD_BIAS) {
            v.x += bsm[u * 4 + 0];
            v.y += bsm[u * 4 + 1];
            v.z += bsm[u * 4 + 2];
            v.w += bsm[u * 4 + 3];
        }
        size_t base = ((size_t)(b0 + rl) * FF + f) * EE + u * 4;
        *reinterpret_cast<float4*>(Yf + base) = v;
    }
}

// ============================================================================
// Stage 2: aggregation via mma.sync bf16-split.
//   out[b,f,e] = sum_g G[b,f,g] * HO[b,g,e]   ([50x50]@[50x64], padded to 64)
// 1 batch/CTA, 128 threads, 32KB smem, occupancy 6 (85-reg budget, no spill).
// HO arrives fp32; staged with the same deterministic hi/lo split as before
// (bit-identical numerics, half the gmem traffic).
// ============================================================================
#define AG_HI 0
#define AG_LO 8192
#define AH_HI 16384
#define AH_LO 24576
#define A_SMEM 32768

__global__ __launch_bounds__(128, 6) void aggr_mma(
    const float* __restrict__ Gm, const float* __restrict__ HO,
    float* __restrict__ out) {
    extern __shared__ char smem[];
    const uint32_t sb = smem_u32(smem);
    const int tid = threadIdx.x, w = tid >> 5, l = tid & 31;
    const int b = blockIdx.x;

    const uint4 z4 = make_uint4(0, 0, 0, 0);
    // Zero G regions (16KB: rows/cols >= 50 must be 0)
    for (int i = tid; i < 1024; i += 128)
        reinterpret_cast<uint4*>(smem)[i] = z4;
    // Zero HO pad rows 50..63 (hi+lo)
    for (int i = tid; i < 224; i += 128) {
        int half = i / 112, rr = i - half * 112;
        int g = 50 + (rr >> 3), u = rr & 7;
        uint32_t off = (uint32_t)(g * 128 + u * 16) ^ (((uint32_t)g & 7u) << 4);
        *reinterpret_cast<uint4*>(smem + AH_HI + half * 8192 + off) = z4;
    }
    __syncthreads();

    // Fill G: float2 loads, bf16 split, u32 stores.
    for (int i = tid; i < 1250; i += 128) {
        int fq = i / 25, g2 = i - fq * 25;
        float2 v = *reinterpret_cast<const float2*>(
            Gm + (size_t)b * (FF * FF) + fq * FF + g2 * 2);
        __nv_bfloat16 h0 = __float2bfloat16_rn(v.x);
        __nv_bfloat16 h1 = __float2bfloat16_rn(v.y);
        __nv_bfloat16 l0 = __float2bfloat16_rn(v.x - __bfloat162float(h0));
        __nv_bfloat16 l1 = __float2bfloat16_rn(v.y - __bfloat162float(h1));
        __nv_bfloat162 hp = __nv_bfloat162(h0, h1);
        __nv_bfloat162 lp = __nv_bfloat162(l0, l1);
        uint32_t off = (uint32_t)(fq * 128 + g2 * 4) ^ (((uint32_t)fq & 7u) << 4);
        *reinterpret_cast<uint32_t*>(smem + AG_HI + off) =
            *reinterpret_cast<uint32_t*>(&hp);
        *reinterpret_cast<uint32_t*>(smem + AG_LO + off) =
            *reinterpret_cast<uint32_t*>(&lp);
    }
    // Fill HO: fp32 float4 loads, split to bf16 hi/lo (same math as before).
    for (int i = tid; i < 800; i += 128) {
        int g = i >> 4, c4 = i & 15;
        float4 v = *reinterpret_cast<const float4*>(
            HO + ((size_t)b * FF + g) * EE + c4 * 4);
        split_store4(smem + AH_HI, smem + AH_LO, g, c4, v);
    }
    __syncthreads();

    const int arow  = w * 16 + (l & 15);
    const int achk  = l >> 4;
    const int bkrow = (l & 7) + (((l >> 3) & 1) << 3);
    const int bchk  = l >> 4;

    float D[8][4] = {};

#pragma unroll
    for (int ks = 0; ks < 4; ks++) {
        uint32_t Ahi[4], Alo[4];
        uint32_t aoff = (uint32_t)(arow * 128) +
                        ((uint32_t)((2 * ks + achk) ^ (arow & 7)) << 4);
        ldsm4(Ahi, sb + AG_HI + aoff);
        ldsm4(Alo, sb + AG_LO + aoff);
#pragma unroll
        for (int p = 0; p < 4; p++) {
            int krow = ks * 16 + bkrow;
            uint32_t boff = (uint32_t)(krow * 128) +
                            ((uint32_t)((2 * p + bchk) ^ (krow & 7)) << 4);
            uint32_t Bhi[4], Blo[4];
            ldsm4t(Bhi, sb + AH_HI + boff);
            ldsm4t(Blo, sb + AH_LO + boff);
            mma16816(D[2 * p],     Ahi, Bhi[0], Bhi[1]);
            mma16816(D[2 * p],     Ahi, Blo[0], Blo[1]);
            mma16816(D[2 * p],     Alo, Bhi[0], Bhi[1]);
            mma16816(D[2 * p + 1], Ahi, Bhi[2], Bhi[3]);
            mma16816(D[2 * p + 1], Ahi, Blo[2], Blo[3]);
            mma16816(D[2 * p + 1], Alo, Bhi[2], Bhi[3]);
        }
    }

    const int r0 = l >> 2, c0 = (l & 3) * 2;
#pragma unroll
    for (int half = 0; half < 2; half++) {
        int frow = w * 16 + r0 + half * 8;
        if (frow < FF) {
            float* orow = out + (size_t)b * (FF * EE) + frow * EE;
#pragma unroll
            for (int nt = 0; nt < 8; nt++)
                *reinterpret_cast<float2*>(orow + nt * 8 + c0) =
                    make_float2(D[nt][2 * half], D[nt][2 * half + 1]);
        }
    }
}

extern "C" void kernel_launch(void* const* d_in, const int* in_sizes, int n_in,
                              void* d_out, int out_size) {
    const float* g     = (const float*)d_in[0];   // [B,F,F]
    const float* h     = (const float*)d_in[1];   // [B,F,E]
    const float* W_in  = (const float*)d_in[2];   // [F,E,E]
    const float* W_out = (const float*)d_in[3];   // [F,E,E]
    const float* bias  = (const float*)d_in[4];   // [E]
    float* out = (float*)d_out;                   // [B,F,E]

    float* ho = nullptr;
    cudaGetSymbolAddress((void**)&ho, g_ho);

    cudaFuncSetAttribute((const void*)field_gemm_mma<false>,
                         cudaFuncAttributeMaxDynamicSharedMemorySize, G_SMEM);
    cudaFuncSetAttribute((const void*)field_gemm_mma<true>,
                         cudaFuncAttributeMaxDynamicSharedMemorySize, G_SMEM);
    cudaFuncSetAttribute((const void*)aggr_mma,
                         cudaFuncAttributeMaxDynamicSharedMemorySize, A_SMEM);

    // Stage 1: ho = einsum('fij,bfj->bfi', W_out, h)   (fp32 out)
    field_gemm_mma<false><<<dim3(BB / 128, FF), 128, G_SMEM>>>(h, W_out, nullptr, ho);
    // Stage 2: out = einsum('bfg,bge->bfe', g, ho)
    aggr_mma<<<BB, 128, A_SMEM>>>(g, ho, out);
    // Stage 3 (in-place): out = einsum('fij,bfj->bfi', W_in, out) + bias
    field_gemm_mma<true><<<dim3(BB / 128, FF), 128, G_SMEM>>>(out, W_in, bias, out);
}

// round 9
// speedup vs baseline: 1.3694x; 1.3694x over previous
#include <cuda_runtime.h>
#include <cuda_bf16.h>
#include <cstdint>

#define BB 16384
#define FF 50
#define EE 64

// Stage-1 intermediate h_out, stored as bf16 hi/lo split (105MB each).
__device__ __nv_bfloat16 g_ho_hi[(size_t)BB * FF * EE];
__device__ __nv_bfloat16 g_ho_lo[(size_t)BB * FF * EE];

// ======================= helpers =======================
__device__ __forceinline__ uint32_t smem_u32(const void* p) {
    uint32_t a;
    asm("{ .reg .u64 t; cvta.to.shared.u64 t, %1; cvt.u32.u64 %0, t; }"
        : "=r"(a) : "l"(p));
    return a;
}
__device__ __forceinline__ void ldsm4(uint32_t* r, uint32_t a) {
    asm volatile("ldmatrix.sync.aligned.m8n8.x4.shared.b16 {%0,%1,%2,%3}, [%4];"
        : "=r"(r[0]), "=r"(r[1]), "=r"(r[2]), "=r"(r[3]) : "r"(a));
}
__device__ __forceinline__ void ldsm4t(uint32_t* r, uint32_t a) {
    asm volatile("ldmatrix.sync.aligned.m8n8.x4.trans.shared.b16 {%0,%1,%2,%3}, [%4];"
        : "=r"(r[0]), "=r"(r[1]), "=r"(r[2]), "=r"(r[3]) : "r"(a));
}
__device__ __forceinline__ void mma16816(float* d, const uint32_t* a,
                                         uint32_t b0, uint32_t b1) {
    asm volatile(
        "mma.sync.aligned.m16n8k16.row.col.f32.bf16.bf16.f32 "
        "{%0,%1,%2,%3}, {%4,%5,%6,%7}, {%8,%9}, {%0,%1,%2,%3};"
        : "+f"(d[0]), "+f"(d[1]), "+f"(d[2]), "+f"(d[3])
        : "r"(a[0]), "r"(a[1]), "r"(a[2]), "r"(a[3]), "r"(b0), "r"(b1));
}
#define CP_ASYNC16(dst, src) \
    asm volatile("cp.async.cg.shared.global [%0], [%1], 16;" \
                 :: "r"(dst), "l"(src) : "memory")
#define CP_COMMIT() asm volatile("cp.async.commit_group;" ::: "memory")
#define CP_WAIT0()  asm volatile("cp.async.wait_group 0;" ::: "memory")

// Convert float4 -> bf16 hi/lo, store into [row][64]bf16 tile (128B rows,
// XOR-(row&7)<<4 permuted so ldmatrix over 8 consecutive rows is conflict-free).
__device__ __forceinline__ void split_store4(char* hiB, char* loB, int row, int c4,
                                             float4 v) {
    __nv_bfloat16 h0 = __float2bfloat16_rn(v.x);
    __nv_bfloat16 h1 = __float2bfloat16_rn(v.y);
    __nv_bfloat16 h2 = __float2bfloat16_rn(v.z);
    __nv_bfloat16 h3 = __float2bfloat16_rn(v.w);
    __nv_bfloat16 l0 = __float2bfloat16_rn(v.x - __bfloat162float(h0));
    __nv_bfloat16 l1 = __float2bfloat16_rn(v.y - __bfloat162float(h1));
    __nv_bfloat16 l2 = __float2bfloat16_rn(v.z - __bfloat162float(h2));
    __nv_bfloat16 l3 = __float2bfloat16_rn(v.w - __bfloat162float(h3));
    __nv_bfloat162 hp0 = __nv_bfloat162(h0, h1), hp1 = __nv_bfloat162(h2, h3);
    __nv_bfloat162 lp0 = __nv_bfloat162(l0, l1), lp1 = __nv_bfloat162(l2, l3);
    uint32_t byte0 = (uint32_t)(row * 128 + c4 * 8);
    uint32_t sw = byte0 ^ (((uint32_t)row & 7u) << 4);
    *reinterpret_cast<uint32_t*>(hiB + sw)     = *reinterpret_cast<uint32_t*>(&hp0);
    *reinterpret_cast<uint32_t*>(hiB + sw + 4) = *reinterpret_cast<uint32_t*>(&hp1);
    *reinterpret_cast<uint32_t*>(loB + sw)     = *reinterpret_cast<uint32_t*>(&lp0);
    *reinterpret_cast<uint32_t*>(loB + sw + 4) = *reinterpret_cast<uint32_t*>(&lp1);
}

// ============================================================================
// Stage 1 / Stage 3: per-field GEMM via mma.sync bf16-split (round-7 measured).
//   Y[b,i] = sum_j X[b,j] * W[f,i,j]
// MODE 0: write bf16 hi/lo split. MODE 1: write fp32 + bias, IN-PLACE on out.
// ============================================================================
#define GX_HI 0
#define GX_LO 16384
#define GW_HI 32768
#define GW_LO 40960
#define G_BIAS 49152
#define G_SMEM 49664

template <int MODE>
__global__ __launch_bounds__(128, 4) void field_gemm_mma(
    const float* __restrict__ X, const float* __restrict__ W,
    const float* __restrict__ bias, float* __restrict__ Yf,
    __nv_bfloat16* __restrict__ Yhi, __nv_bfloat16* __restrict__ Ylo) {
    extern __shared__ char smem[];
    const uint32_t sb = smem_u32(smem);
    const int tid = threadIdx.x, w = tid >> 5, l = tid & 31;
    const int f = blockIdx.y, b0 = blockIdx.x * 128;

    if (MODE == 1 && tid < 16)
        reinterpret_cast<float4*>(smem + G_BIAS)[tid] =
            reinterpret_cast<const float4*>(bias)[tid];

    const float* Xb = X + (size_t)b0 * (FF * EE) + (size_t)f * EE;
#pragma unroll
    for (int t = 0; t < 16; t++) {
        int idx = tid + t * 128;
        int b = idx >> 4, c4 = idx & 15;
        float4 v = *reinterpret_cast<const float4*>(Xb + (size_t)b * (FF * EE) + c4 * 4);
        split_store4(smem + GX_HI, smem + GX_LO, b, c4, v);
    }
    const float* Wf = W + (size_t)f * EE * EE;
#pragma unroll
    for (int t = 0; t < 8; t++) {
        int idx = tid + t * 128;
        int n = idx >> 4, c4 = idx & 15;
        float4 v = *reinterpret_cast<const float4*>(Wf + n * EE + c4 * 4);
        split_store4(smem + GW_HI, smem + GW_LO, n, c4, v);
    }
    __syncthreads();

    const int arow0 = w * 32 + (l & 15);
    const int achk  = l >> 4;
    const int brow  = (l & 7) + ((l >> 4) << 3);
    const int bchk  = (l >> 3) & 1;

    float D[2][8][4] = {};

#pragma unroll
    for (int ks = 0; ks < 4; ks++) {
        uint32_t Ahi[2][4], Alo[2][4];
#pragma unroll
        for (int mt = 0; mt < 2; mt++) {
            int row = arow0 + mt * 16;
            uint32_t off = (uint32_t)(row * 128) +
                           ((uint32_t)((2 * ks + achk) ^ (row & 7)) << 4);
            ldsm4(Ahi[mt], sb + GX_HI + off);
            ldsm4(Alo[mt], sb + GX_LO + off);
        }
#pragma unroll
        for (int p = 0; p < 4; p++) {
            int nrow = p * 16 + brow;
            uint32_t off = (uint32_t)(nrow * 128) +
                           ((uint32_t)((2 * ks + bchk) ^ (nrow & 7)) << 4);
            uint32_t Bhi[4], Blo[4];
            ldsm4(Bhi, sb + GW_HI + off);
            ldsm4(Blo, sb + GW_LO + off);
#pragma unroll
            for (int mt = 0; mt < 2; mt++) {
                mma16816(D[mt][2 * p],     Ahi[mt], Bhi[0], Bhi[1]);
                mma16816(D[mt][2 * p],     Ahi[mt], Blo[0], Blo[1]);
                mma16816(D[mt][2 * p],     Alo[mt], Bhi[0], Bhi[1]);
                mma16816(D[mt][2 * p + 1], Ahi[mt], Bhi[2], Bhi[3]);
                mma16816(D[mt][2 * p + 1], Ahi[mt], Blo[2], Blo[3]);
                mma16816(D[mt][2 * p + 1], Alo[mt], Bhi[2], Bhi[3]);
            }
        }
    }

    __syncthreads();   // done reading X/W smem; reuse [0, 32KB)
    const int r0 = l >> 2, c0 = (l & 3) * 2;
    if (MODE == 0) {
#pragma unroll
        for (int mt = 0; mt < 2; mt++)
#pragma unroll
            for (int half = 0; half < 2; half++) {
                int rl = w * 32 + mt * 16 + half * 8 + r0;
                uint32_t rsw = ((uint32_t)rl & 7u) << 4;
#pragma unroll
                for (int nt = 0; nt < 8; nt++) {
                    float vx = D[mt][nt][2 * half], vy = D[mt][nt][2 * half + 1];
                    __nv_bfloat16 h0 = __float2bfloat16_rn(vx);
                    __nv_bfloat16 h1 = __float2bfloat16_rn(vy);
                    __nv_bfloat16 l0 = __float2bfloat16_rn(vx - __bfloat162float(h0));
                    __nv_bfloat16 l1 = __float2bfloat16_rn(vy - __bfloat162float(h1));
                    __nv_bfloat162 hp = __nv_bfloat162(h0, h1);
                    __nv_bfloat162 lp = __nv_bfloat162(l0, l1);
                    uint32_t off = (uint32_t)(rl * 128) +
                                   (((uint32_t)((nt * 8 + c0) * 2)) ^ rsw);
                    *reinterpret_cast<uint32_t*>(smem + off) =
                        *reinterpret_cast<uint32_t*>(&hp);
                    *reinterpret_cast<uint32_t*>(smem + 16384 + off) =
                        *reinterpret_cast<uint32_t*>(&lp);
                }
            }
        __syncthreads();
#pragma unroll
        for (int it = 0; it < 8; it++) {
            int rl = w * 32 + it * 4 + (l >> 3);
            int u  = l & 7;
            uint32_t off = (uint32_t)(rl * 128) +
                           (((uint32_t)(u * 16)) ^ (((uint32_t)rl & 7u) << 4));
            uint4 vhi = *reinterpret_cast<const uint4*>(smem + off);
            uint4 vlo = *reinterpret_cast<const uint4*>(smem + 16384 + off);
            size_t base = ((size_t)(b0 + rl) * FF + f) * EE + u * 8;
            *reinterpret_cast<uint4*>(Yhi + base) = vhi;
            *reinterpret_cast<uint4*>(Ylo + base) = vlo;
        }
    } else {
#pragma unroll
        for (int mt = 0; mt < 2; mt++)
#pragma unroll
            for (int half = 0; half < 2; half++) {
                int rl = w * 32 + mt * 16 + half * 8 + r0;
                uint32_t rsw = ((uint32_t)rl & 7u) << 4;
#pragma unroll
                for (int nt = 0; nt < 8; nt++) {
                    float2 v = make_float2(D[mt][nt][2 * half], D[mt][nt][2 * half + 1]);
                    uint32_t off = (uint32_t)(rl * 256) +
                                   (((uint32_t)((nt * 8 + c0) * 4)) ^ rsw);
                    *reinterpret_cast<float2*>(smem + off) = v;
                }
            }
        __syncthreads();
        const float* bsm = reinterpret_cast<const float*>(smem + G_BIAS);
#pragma unroll
        for (int it = 0; it < 16; it++) {
            int rl = w * 32 + it * 2 + (l >> 4);
            int u  = l & 15;
            uint32_t off = (uint32_t)(rl * 256) +
                           (((uint32_t)(u * 16)) ^ (((uint32_t)rl & 7u) << 4));
            float4 v = *reinterpret_cast<const float4*>(smem + off);
            v.x += bsm[u * 4 + 0];
            v.y += bsm[u * 4 + 1];
            v.z += bsm[u * 4 + 2];
            v.w += bsm[u * 4 + 3];
            size_t base = ((size_t)(b0 + rl) * FF + f) * EE + u * 4;
            *reinterpret_cast<float4*>(Yf + base) = v;
        }
    }
}

// ============================================================================
// Stage 2: PERSISTENT double-buffered aggregation.
//   out[b,f,e] = sum_g G[b,f,g] * HO[b,g,e]
// 456 CTAs x 128 threads; each loops over batches b, b+grid, ...
// Per iteration: wait cp.async group for b -> prefetch b+grid (HO = pure 16B
// copies into final swizzled slots; G raw fp32) -> convert G -> MMA -> store.
// smem 68KB -> occ 3. Prefetch overlaps convert+MMA+stores of current batch.
// ============================================================================
#define HOF(s)  ((s) * 16384)          // hi +0, lo +8192
#define AGF_HI  32768
#define AGF_LO  40960
#define GRAW(s) (49152 + (s) * 10240)  // 10000B raw fp32 G
#define A_SMEM  69632
#define AGGR_GRID 456

__global__ __launch_bounds__(128) void aggr_mma(
    const float* __restrict__ Gm,
    const __nv_bfloat16* __restrict__ HOhi, const __nv_bfloat16* __restrict__ HOlo,
    float* __restrict__ out) {
    extern __shared__ char smem[];
    const uint32_t sb = smem_u32(smem);
    const int tid = threadIdx.x, w = tid >> 5, l = tid & 31;

    // One-time zeroing: GF entirely (pads f>=50 / g>=50 stay 0 forever; every
    // batch rewrites rows 0..49 cols 0..49 fully), HO pad rows 50..63 (both
    // stages; never overwritten by copies).
    const uint4 z4 = make_uint4(0, 0, 0, 0);
    for (int i = tid; i < 1024; i += 128)
        reinterpret_cast<uint4*>(smem + AGF_HI)[i] = z4;
    for (int i = tid; i < 448; i += 128) {
        int s = i / 224, r = i - s * 224;
        int half = r / 112, rr = r - half * 112;
        int g = 50 + (rr >> 3), u = rr & 7;
        uint32_t off = (uint32_t)(g * 128 + u * 16) ^ (((uint32_t)g & 7u) << 4);
        *reinterpret_cast<uint4*>(smem + HOF(s) + half * 8192 + off) = z4;
    }
    __syncthreads();

    // lane geometry (constant across batches)
    const int arow  = w * 16 + (l & 15);
    const int achk  = l >> 4;
    const int bkrow = (l & 7) + (((l >> 3) & 1) << 3);
    const int bchk  = l >> 4;
    const uint32_t aoff_base = (uint32_t)(arow * 128);

    // Prefetch first batch into stage 0.
    int b0 = blockIdx.x;
    auto issue_loads = [&](int b, int st) {
        // HO hi/lo: pure 16B copies into final swizzled positions.
        for (int i = tid; i < 800; i += 128) {
            int half = (i >= 400);
            int rr = i - half * 400;
            int g = rr >> 3, u = rr & 7;
            const __nv_bfloat16* src = (half ? HOlo : HOhi) +
                ((size_t)b * FF + g) * EE + u * 8;
            uint32_t off = (uint32_t)(g * 128 + u * 16) ^ (((uint32_t)g & 7u) << 4);
            CP_ASYNC16(sb + HOF(st) + half * 8192 + off, src);
        }
        // G raw fp32: 625 x 16B contiguous.
        for (int i = tid; i < 625; i += 128)
            CP_ASYNC16(sb + GRAW(st) + i * 16, Gm + (size_t)b * (FF * FF) + i * 4);
    };

    if (b0 < BB) issue_loads(b0, 0);
    CP_COMMIT();

    int s = 0;
    for (int b = b0; b < BB; b += AGGR_GRID) {
        CP_WAIT0();
        __syncthreads();

        int nb = b + AGGR_GRID;
        if (nb < BB) issue_loads(nb, s ^ 1);
        CP_COMMIT();

        // Convert G raw fp32 -> bf16 hi/lo into GF (LDS reads, cheap).
        const char* graw = smem + GRAW(s);
        for (int i = tid; i < 1250; i += 128) {
            int fq = i / 25, g2 = i - fq * 25;
            float2 v = *reinterpret_cast<const float2*>(graw + (fq * 50 + g2 * 2) * 4);
            __nv_bfloat16 h0 = __float2bfloat16_rn(v.x);
            __nv_bfloat16 h1 = __float2bfloat16_rn(v.y);
            __nv_bfloat16 l0 = __float2bfloat16_rn(v.x - __bfloat162float(h0));
            __nv_bfloat16 l1 = __float2bfloat16_rn(v.y - __bfloat162float(h1));
            __nv_bfloat162 hp = __nv_bfloat162(h0, h1);
            __nv_bfloat162 lp = __nv_bfloat162(l0, l1);
            uint32_t off = (uint32_t)(fq * 128 + g2 * 4) ^ (((uint32_t)fq & 7u) << 4);
            *reinterpret_cast<uint32_t*>(smem + AGF_HI + off) =
                *reinterpret_cast<uint32_t*>(&hp);
            *reinterpret_cast<uint32_t*>(smem + AGF_LO + off) =
                *reinterpret_cast<uint32_t*>(&lp);
        }
        __syncthreads();

        float D[8][4] = {};
#pragma unroll
        for (int ks = 0; ks < 4; ks++) {
            uint32_t Ahi[4], Alo[4];
            uint32_t aoff = aoff_base +
                            ((uint32_t)((2 * ks + achk) ^ (arow & 7)) << 4);
            ldsm4(Ahi, sb + AGF_HI + aoff);
            ldsm4(Alo, sb + AGF_LO + aoff);
#pragma unroll
            for (int p = 0; p < 4; p++) {
                int krow = ks * 16 + bkrow;
                uint32_t boff = (uint32_t)(krow * 128) +
                                ((uint32_t)((2 * p + bchk) ^ (krow & 7)) << 4);
                uint32_t Bhi[4], Blo[4];
                ldsm4t(Bhi, sb + HOF(s) + boff);
                ldsm4t(Blo, sb + HOF(s) + 8192 + boff);
                mma16816(D[2 * p],     Ahi, Bhi[0], Bhi[1]);
                mma16816(D[2 * p],     Ahi, Blo[0], Blo[1]);
                mma16816(D[2 * p],     Alo, Bhi[0], Bhi[1]);
                mma16816(D[2 * p + 1], Ahi, Bhi[2], Bhi[3]);
                mma16816(D[2 * p + 1], Ahi, Blo[2], Blo[3]);
                mma16816(D[2 * p + 1], Alo, Bhi[2], Bhi[3]);
            }
        }

        const int r0 = l >> 2, c0 = (l & 3) * 2;
#pragma unroll
        for (int half = 0; half < 2; half++) {
            int frow = w * 16 + r0 + half * 8;
            if (frow < FF) {
                float* orow = out + (size_t)b * (FF * EE) + frow * EE;
#pragma unroll
                for (int nt = 0; nt < 8; nt++)
                    *reinterpret_cast<float2*>(orow + nt * 8 + c0) =
                        make_float2(D[nt][2 * half], D[nt][2 * half + 1]);
            }
        }
        __syncthreads();   // all warps done reading GF/HOF(s) before next iter
        s ^= 1;
    }
}

extern "C" void kernel_launch(void* const* d_in, const int* in_sizes, int n_in,
                              void* d_out, int out_size) {
    const float* g     = (const float*)d_in[0];   // [B,F,F]
    const float* h     = (const float*)d_in[1];   // [B,F,E]
    const float* W_in  = (const float*)d_in[2];   // [F,E,E]
    const float* W_out = (const float*)d_in[3];   // [F,E,E]
    const float* bias  = (const float*)d_in[4];   // [E]
    float* out = (float*)d_out;                   // [B,F,E]

    __nv_bfloat16 *hohi = nullptr, *holo = nullptr;
    cudaGetSymbolAddress((void**)&hohi, g_ho_hi);
    cudaGetSymbolAddress((void**)&holo, g_ho_lo);

    cudaFuncSetAttribute((const void*)field_gemm_mma<0>,
                         cudaFuncAttributeMaxDynamicSharedMemorySize, G_SMEM);
    cudaFuncSetAttribute((const void*)field_gemm_mma<1>,
                         cudaFuncAttributeMaxDynamicSharedMemorySize, G_SMEM);
    cudaFuncSetAttribute((const void*)aggr_mma,
                         cudaFuncAttributeMaxDynamicSharedMemorySize, A_SMEM);

    // Stage 1: ho(hi/lo) = split( einsum('fij,bfj->bfi', W_out, h) )
    field_gemm_mma<0><<<dim3(BB / 128, FF), 128, G_SMEM>>>(
        h, W_out, nullptr, nullptr, hohi, holo);
    // Stage 2: out = einsum('bfg,bge->bfe', g, ho)   (persistent pipeline)
    aggr_mma<<<AGGR_GRID, 128, A_SMEM>>>(g, hohi, holo, out);
    // Stage 3 (in-place): out = einsum('fij,bfj->bfi', W_in, out) + bias
    field_gemm_mma<1><<<dim3(BB / 128, FF), 128, G_SMEM>>>(
        out, W_in, bias, out, nullptr, nullptr);
}

// round 10
// speedup vs baseline: 1.4090x; 1.0289x over previous
#include <cuda_runtime.h>
#include <cuda_bf16.h>
#include <cstdint>

#define BB 16384
#define FF 50
#define EE 64

// Stage-1 intermediate h_out, stored as bf16 hi/lo split (105MB each).
__device__ __nv_bfloat16 g_ho_hi[(size_t)BB * FF * EE];
__device__ __nv_bfloat16 g_ho_lo[(size_t)BB * FF * EE];

// ======================= helpers =======================
__device__ __forceinline__ uint32_t smem_u32(const void* p) {
    uint32_t a;
    asm("{ .reg .u64 t; cvta.to.shared.u64 t, %1; cvt.u32.u64 %0, t; }"
        : "=r"(a) : "l"(p));
    return a;
}
__device__ __forceinline__ void ldsm4(uint32_t* r, uint32_t a) {
    asm volatile("ldmatrix.sync.aligned.m8n8.x4.shared.b16 {%0,%1,%2,%3}, [%4];"
        : "=r"(r[0]), "=r"(r[1]), "=r"(r[2]), "=r"(r[3]) : "r"(a));
}
__device__ __forceinline__ void ldsm4t(uint32_t* r, uint32_t a) {
    asm volatile("ldmatrix.sync.aligned.m8n8.x4.trans.shared.b16 {%0,%1,%2,%3}, [%4];"
        : "=r"(r[0]), "=r"(r[1]), "=r"(r[2]), "=r"(r[3]) : "r"(a));
}
__device__ __forceinline__ void mma16816(float* d, const uint32_t* a,
                                         uint32_t b0, uint32_t b1) {
    asm volatile(
        "mma.sync.aligned.m16n8k16.row.col.f32.bf16.bf16.f32 "
        "{%0,%1,%2,%3}, {%4,%5,%6,%7}, {%8,%9}, {%0,%1,%2,%3};"
        : "+f"(d[0]), "+f"(d[1]), "+f"(d[2]), "+f"(d[3])
        : "r"(a[0]), "r"(a[1]), "r"(a[2]), "r"(a[3]), "r"(b0), "r"(b1));
}
#define CP_ASYNC16(dst, src) \
    asm volatile("cp.async.cg.shared.global [%0], [%1], 16;" \
                 :: "r"(dst), "l"(src) : "memory")
#define CP_COMMIT() asm volatile("cp.async.commit_group;" ::: "memory")
#define CP_WAIT0()  asm volatile("cp.async.wait_group 0;" ::: "memory")

// Convert float4 -> bf16 hi/lo, store into [row][64]bf16 tile (128B rows,
// XOR-(row&7)<<4 permuted so ldmatrix over 8 consecutive rows is conflict-free).
__device__ __forceinline__ void split_store4(char* hiB, char* loB, int row, int c4,
                                             float4 v) {
    __nv_bfloat16 h0 = __float2bfloat16_rn(v.x);
    __nv_bfloat16 h1 = __float2bfloat16_rn(v.y);
    __nv_bfloat16 h2 = __float2bfloat16_rn(v.z);
    __nv_bfloat16 h3 = __float2bfloat16_rn(v.w);
    __nv_bfloat16 l0 = __float2bfloat16_rn(v.x - __bfloat162float(h0));
    __nv_bfloat16 l1 = __float2bfloat16_rn(v.y - __bfloat162float(h1));
    __nv_bfloat16 l2 = __float2bfloat16_rn(v.z - __bfloat162float(h2));
    __nv_bfloat16 l3 = __float2bfloat16_rn(v.w - __bfloat162float(h3));
    __nv_bfloat162 hp0 = __nv_bfloat162(h0, h1), hp1 = __nv_bfloat162(h2, h3);
    __nv_bfloat162 lp0 = __nv_bfloat162(l0, l1), lp1 = __nv_bfloat162(l2, l3);
    uint32_t byte0 = (uint32_t)(row * 128 + c4 * 8);
    uint32_t sw = byte0 ^ (((uint32_t)row & 7u) << 4);
    *reinterpret_cast<uint32_t*>(hiB + sw)     = *reinterpret_cast<uint32_t*>(&hp0);
    *reinterpret_cast<uint32_t*>(hiB + sw + 4) = *reinterpret_cast<uint32_t*>(&hp1);
    *reinterpret_cast<uint32_t*>(loB + sw)     = *reinterpret_cast<uint32_t*>(&lp0);
    *reinterpret_cast<uint32_t*>(loB + sw + 4) = *reinterpret_cast<uint32_t*>(&lp1);
}

// ============================================================================
// Stage 1: per-field GEMM via mma.sync bf16-split (round-7/9 measured config).
//   ho[b,i] = sum_j h[b,j] * W_out[f,i,j], written as bf16 hi/lo split.
// Grid (B/128, F), 128 threads (4 warps). CTA tile 128b x 64i, K=64.
// ============================================================================
#define GX_HI 0
#define GX_LO 16384
#define GW_HI 32768
#define GW_LO 40960
#define G_SMEM 49664

__global__ __launch_bounds__(128, 4) void field_gemm_mma(
    const float* __restrict__ X, const float* __restrict__ W,
    __nv_bfloat16* __restrict__ Yhi, __nv_bfloat16* __restrict__ Ylo) {
    extern __shared__ char smem[];
    const uint32_t sb = smem_u32(smem);
    const int tid = threadIdx.x, w = tid >> 5, l = tid & 31;
    const int f = blockIdx.y, b0 = blockIdx.x * 128;

    const float* Xb = X + (size_t)b0 * (FF * EE) + (size_t)f * EE;
#pragma unroll
    for (int t = 0; t < 16; t++) {
        int idx = tid + t * 128;
        int b = idx >> 4, c4 = idx & 15;
        float4 v = *reinterpret_cast<const float4*>(Xb + (size_t)b * (FF * EE) + c4 * 4);
        split_store4(smem + GX_HI, smem + GX_LO, b, c4, v);
    }
    const float* Wf = W + (size_t)f * EE * EE;
#pragma unroll
    for (int t = 0; t < 8; t++) {
        int idx = tid + t * 128;
        int n = idx >> 4, c4 = idx & 15;
        float4 v = *reinterpret_cast<const float4*>(Wf + n * EE + c4 * 4);
        split_store4(smem + GW_HI, smem + GW_LO, n, c4, v);
    }
    __syncthreads();

    const int arow0 = w * 32 + (l & 15);
    const int achk  = l >> 4;
    const int brow  = (l & 7) + ((l >> 4) << 3);
    const int bchk  = (l >> 3) & 1;

    float D[2][8][4] = {};

#pragma unroll
    for (int ks = 0; ks < 4; ks++) {
        uint32_t Ahi[2][4], Alo[2][4];
#pragma unroll
        for (int mt = 0; mt < 2; mt++) {
            int row = arow0 + mt * 16;
            uint32_t off = (uint32_t)(row * 128) +
                           ((uint32_t)((2 * ks + achk) ^ (row & 7)) << 4);
            ldsm4(Ahi[mt], sb + GX_HI + off);
            ldsm4(Alo[mt], sb + GX_LO + off);
        }
#pragma unroll
        for (int p = 0; p < 4; p++) {
            int nrow = p * 16 + brow;
            uint32_t off = (uint32_t)(nrow * 128) +
                           ((uint32_t)((2 * ks + bchk) ^ (nrow & 7)) << 4);
            uint32_t Bhi[4], Blo[4];
            ldsm4(Bhi, sb + GW_HI + off);
            ldsm4(Blo, sb + GW_LO + off);
#pragma unroll
            for (int mt = 0; mt < 2; mt++) {
                mma16816(D[mt][2 * p],     Ahi[mt], Bhi[0], Bhi[1]);
                mma16816(D[mt][2 * p],     Ahi[mt], Blo[0], Blo[1]);
                mma16816(D[mt][2 * p],     Alo[mt], Bhi[0], Bhi[1]);
                mma16816(D[mt][2 * p + 1], Ahi[mt], Bhi[2], Bhi[3]);
                mma16816(D[mt][2 * p + 1], Ahi[mt], Blo[2], Blo[3]);
                mma16816(D[mt][2 * p + 1], Alo[mt], Bhi[2], Bhi[3]);
            }
        }
    }

    __syncthreads();   // done reading X/W smem; reuse [0, 32KB)
    const int r0 = l >> 2, c0 = (l & 3) * 2;
#pragma unroll
    for (int mt = 0; mt < 2; mt++)
#pragma unroll
        for (int half = 0; half < 2; half++) {
            int rl = w * 32 + mt * 16 + half * 8 + r0;
            uint32_t rsw = ((uint32_t)rl & 7u) << 4;
#pragma unroll
            for (int nt = 0; nt < 8; nt++) {
                float vx = D[mt][nt][2 * half], vy = D[mt][nt][2 * half + 1];
                __nv_bfloat16 h0 = __float2bfloat16_rn(vx);
                __nv_bfloat16 h1 = __float2bfloat16_rn(vy);
                __nv_bfloat16 l0 = __float2bfloat16_rn(vx - __bfloat162float(h0));
                __nv_bfloat16 l1 = __float2bfloat16_rn(vy - __bfloat162float(h1));
                __nv_bfloat162 hp = __nv_bfloat162(h0, h1);
                __nv_bfloat162 lp = __nv_bfloat162(l0, l1);
                uint32_t off = (uint32_t)(rl * 128) +
                               (((uint32_t)((nt * 8 + c0) * 2)) ^ rsw);
                *reinterpret_cast<uint32_t*>(smem + off) =
                    *reinterpret_cast<uint32_t*>(&hp);
                *reinterpret_cast<uint32_t*>(smem + 16384 + off) =
                    *reinterpret_cast<uint32_t*>(&lp);
            }
        }
    __syncthreads();
#pragma unroll
    for (int it = 0; it < 8; it++) {
        int rl = w * 32 + it * 4 + (l >> 3);
        int u  = l & 7;
        uint32_t off = (uint32_t)(rl * 128) +
                       (((uint32_t)(u * 16)) ^ (((uint32_t)rl & 7u) << 4));
        uint4 vhi = *reinterpret_cast<const uint4*>(smem + off);
        uint4 vlo = *reinterpret_cast<const uint4*>(smem + 16384 + off);
        size_t base = ((size_t)(b0 + rl) * FF + f) * EE + u * 8;
        *reinterpret_cast<uint4*>(Yhi + base) = vhi;
        *reinterpret_cast<uint4*>(Ylo + base) = vlo;
    }
}

// ============================================================================
// Stage 2: PERSISTENT double-buffered aggregation (round-9 measured, grid 444).
//   out[b,f,e] = sum_g G[b,f,g] * HO[b,g,e]   -> fp32 into d_out
// ============================================================================
#define HOF(s)  ((s) * 16384)          // hi +0, lo +8192
#define AGF_HI  32768
#define AGF_LO  40960
#define GRAW(s) (49152 + (s) * 10240)  // 10000B raw fp32 G
#define A_SMEM  69632
#define AGGR_GRID 444

__global__ __launch_bounds__(128) void aggr_mma(
    const float* __restrict__ Gm,
    const __nv_bfloat16* __restrict__ HOhi, const __nv_bfloat16* __restrict__ HOlo,
    float* __restrict__ out) {
    extern __shared__ char smem[];
    const uint32_t sb = smem_u32(smem);
    const int tid = threadIdx.x, w = tid >> 5, l = tid & 31;

    const uint4 z4 = make_uint4(0, 0, 0, 0);
    for (int i = tid; i < 1024; i += 128)
        reinterpret_cast<uint4*>(smem + AGF_HI)[i] = z4;
    for (int i = tid; i < 448; i += 128) {
        int s = i / 224, r = i - s * 224;
        int half = r / 112, rr = r - half * 112;
        int g = 50 + (rr >> 3), u = rr & 7;
        uint32_t off = (uint32_t)(g * 128 + u * 16) ^ (((uint32_t)g & 7u) << 4);
        *reinterpret_cast<uint4*>(smem + HOF(s) + half * 8192 + off) = z4;
    }
    __syncthreads();

    const int arow  = w * 16 + (l & 15);
    const int achk  = l >> 4;
    const int bkrow = (l & 7) + (((l >> 3) & 1) << 3);
    const int bchk  = l >> 4;
    const uint32_t aoff_base = (uint32_t)(arow * 128);

    int b0 = blockIdx.x;
    auto issue_loads = [&](int b, int st) {
        for (int i = tid; i < 800; i += 128) {
            int half = (i >= 400);
            int rr = i - half * 400;
            int g = rr >> 3, u = rr & 7;
            const __nv_bfloat16* src = (half ? HOlo : HOhi) +
                ((size_t)b * FF + g) * EE + u * 8;
            uint32_t off = (uint32_t)(g * 128 + u * 16) ^ (((uint32_t)g & 7u) << 4);
            CP_ASYNC16(sb + HOF(st) + half * 8192 + off, src);
        }
        for (int i = tid; i < 625; i += 128)
            CP_ASYNC16(sb + GRAW(st) + i * 16, Gm + (size_t)b * (FF * FF) + i * 4);
    };

    if (b0 < BB) issue_loads(b0, 0);
    CP_COMMIT();

    int s = 0;
    for (int b = b0; b < BB; b += AGGR_GRID) {
        CP_WAIT0();
        __syncthreads();

        int nb = b + AGGR_GRID;
        if (nb < BB) issue_loads(nb, s ^ 1);
        CP_COMMIT();

        const char* graw = smem + GRAW(s);
        for (int i = tid; i < 1250; i += 128) {
            int fq = i / 25, g2 = i - fq * 25;
            float2 v = *reinterpret_cast<const float2*>(graw + (fq * 50 + g2 * 2) * 4);
            __nv_bfloat16 h0 = __float2bfloat16_rn(v.x);
            __nv_bfloat16 h1 = __float2bfloat16_rn(v.y);
            __nv_bfloat16 l0 = __float2bfloat16_rn(v.x - __bfloat162float(h0));
            __nv_bfloat16 l1 = __float2bfloat16_rn(v.y - __bfloat162float(h1));
            __nv_bfloat162 hp = __nv_bfloat162(h0, h1);
            __nv_bfloat162 lp = __nv_bfloat162(l0, l1);
            uint32_t off = (uint32_t)(fq * 128 + g2 * 4) ^ (((uint32_t)fq & 7u) << 4);
            *reinterpret_cast<uint32_t*>(smem + AGF_HI + off) =
                *reinterpret_cast<uint32_t*>(&hp);
            *reinterpret_cast<uint32_t*>(smem + AGF_LO + off) =
                *reinterpret_cast<uint32_t*>(&lp);
        }
        __syncthreads();

        float D[8][4] = {};
#pragma unroll
        for (int ks = 0; ks < 4; ks++) {
            uint32_t Ahi[4], Alo[4];
            uint32_t aoff = aoff_base +
                            ((uint32_t)((2 * ks + achk) ^ (arow & 7)) << 4);
            ldsm4(Ahi, sb + AGF_HI + aoff);
            ldsm4(Alo, sb + AGF_LO + aoff);
#pragma unroll
            for (int p = 0; p < 4; p++) {
                int krow = ks * 16 + bkrow;
                uint32_t boff = (uint32_t)(krow * 128) +
                                ((uint32_t)((2 * p + bchk) ^ (krow & 7)) << 4);
                uint32_t Bhi[4], Blo[4];
                ldsm4t(Bhi, sb + HOF(s) + boff);
                ldsm4t(Blo, sb + HOF(s) + 8192 + boff);
                mma16816(D[2 * p],     Ahi, Bhi[0], Bhi[1]);
                mma16816(D[2 * p],     Ahi, Blo[0], Blo[1]);
                mma16816(D[2 * p],     Alo, Bhi[0], Bhi[1]);
                mma16816(D[2 * p + 1], Ahi, Bhi[2], Bhi[3]);
                mma16816(D[2 * p + 1], Ahi, Blo[2], Blo[3]);
                mma16816(D[2 * p + 1], Alo, Bhi[2], Bhi[3]);
            }
        }

        const int r0 = l >> 2, c0 = (l & 3) * 2;
#pragma unroll
        for (int half = 0; half < 2; half++) {
            int frow = w * 16 + r0 + half * 8;
            if (frow < FF) {
                float* orow = out + (size_t)b * (FF * EE) + frow * EE;
#pragma unroll
                for (int nt = 0; nt < 8; nt++)
                    *reinterpret_cast<float2*>(orow + nt * 8 + c0) =
                        make_float2(D[nt][2 * half], D[nt][2 * half + 1]);
            }
        }
        __syncthreads();
        s ^= 1;
    }
}

// ============================================================================
// Stage 3: PERSISTENT pipelined per-field GEMM, IN-PLACE on d_out.
//   out[b,f,i] = sum_j W_in[f,i,j] * out[b,f,j] + bias[i]
// Grid (8, 50): CTA (c, f) owns field f and b-tiles c, c+8, ... (32 tiles of
// 64 rows). W_in[f] hi/lo + bias staged ONCE. Per iter: wait raw-X group ->
// prefetch next tile raw fp32 (cp.async 16B) -> convert raw -> bf16 hi/lo ->
// MMA -> fp32+bias stores. In-place safe: CTA only touches its own f-rows and
// reads each tile before writing it.
// ============================================================================
#define S3_RAW(s) ((s) * 16384)   // 64 rows x 256B raw fp32
#define S3_XHI    32768
#define S3_XLO    40960
#define S3_WHI    49152
#define S3_WLO    57344
#define S3_BIAS   65536
#define S3_SMEM   65792
#define S3_CPF    8               // CTAs per field

__global__ __launch_bounds__(128) void field3_pipe(
    const float* __restrict__ W, const float* __restrict__ bias, float* out) {
    extern __shared__ char smem[];
    const uint32_t sb = smem_u32(smem);
    const int tid = threadIdx.x, w = tid >> 5, l = tid & 31;
    const int f = blockIdx.y, c = blockIdx.x;

    // Stage W_in[f] hi/lo once.
    const float* Wf = W + (size_t)f * EE * EE;
#pragma unroll
    for (int t = 0; t < 8; t++) {
        int idx = tid + t * 128;
        int n = idx >> 4, c4 = idx & 15;
        float4 v = *reinterpret_cast<const float4*>(Wf + n * EE + c4 * 4);
        split_store4(smem + S3_WHI, smem + S3_WLO, n, c4, v);
    }
    if (tid < 16)
        reinterpret_cast<float4*>(smem + S3_BIAS)[tid] =
            reinterpret_cast<const float4*>(bias)[tid];

    auto issue = [&](int bt, int st) {
        // 64 rows x 16 chunks of 16B raw fp32.
        for (int i = tid; i < 1024; i += 128) {
            int row = i >> 4, u = i & 15;
            const float* src = out + ((size_t)(bt * 64 + row) * FF + f) * EE + u * 4;
            CP_ASYNC16(sb + S3_RAW(st) + row * 256 + u * 16, src);
        }
    };

    issue(c, 0);
    CP_COMMIT();

    const int arow = w * 16 + (l & 15);
    const int achk = l >> 4;
    const int brow = (l & 7) + ((l >> 4) << 3);
    const int bchk = (l >> 3) & 1;

    int s = 0;
    for (int bt = c; bt < 256; bt += S3_CPF) {
        CP_WAIT0();
        __syncthreads();

        int nbt = bt + S3_CPF;
        if (nbt < 256) issue(nbt, s ^ 1);
        CP_COMMIT();

        // Convert raw fp32 tile -> bf16 hi/lo (swizzled), float2 granularity.
        const char* raw = smem + S3_RAW(s);
        for (int i = tid; i < 2048; i += 128) {
            int row = i >> 5, p2 = i & 31;
            float2 v = *reinterpret_cast<const float2*>(raw + row * 256 + p2 * 8);
            __nv_bfloat16 h0 = __float2bfloat16_rn(v.x);
            __nv_bfloat16 h1 = __float2bfloat16_rn(v.y);
            __nv_bfloat16 l0 = __float2bfloat16_rn(v.x - __bfloat162float(h0));
            __nv_bfloat16 l1 = __float2bfloat16_rn(v.y - __bfloat162float(h1));
            __nv_bfloat162 hp = __nv_bfloat162(h0, h1);
            __nv_bfloat162 lp = __nv_bfloat162(l0, l1);
            uint32_t off = (uint32_t)(row * 128 + p2 * 4) ^ (((uint32_t)row & 7u) << 4);
            *reinterpret_cast<uint32_t*>(smem + S3_XHI + off) =
                *reinterpret_cast<uint32_t*>(&hp);
            *reinterpret_cast<uint32_t*>(smem + S3_XLO + off) =
                *reinterpret_cast<uint32_t*>(&lp);
        }
        __syncthreads();

        float D[8][4] = {};
#pragma unroll
        for (int ks = 0; ks < 4; ks++) {
            uint32_t Ahi[4], Alo[4];
            uint32_t aoff = (uint32_t)(arow * 128) +
                            ((uint32_t)((2 * ks + achk) ^ (arow & 7)) << 4);
            ldsm4(Ahi, sb + S3_XHI + aoff);
            ldsm4(Alo, sb + S3_XLO + aoff);
#pragma unroll
            for (int p = 0; p < 4; p++) {
                int nrow = p * 16 + brow;
                uint32_t boff = (uint32_t)(nrow * 128) +
                                ((uint32_t)((2 * ks + bchk) ^ (nrow & 7)) << 4);
                uint32_t Bhi[4], Blo[4];
                ldsm4(Bhi, sb + S3_WHI + boff);
                ldsm4(Blo, sb + S3_WLO + boff);
                mma16816(D[2 * p],     Ahi, Bhi[0], Bhi[1]);
                mma16816(D[2 * p],     Ahi, Blo[0], Blo[1]);
                mma16816(D[2 * p],     Alo, Bhi[0], Bhi[1]);
                mma16816(D[2 * p + 1], Ahi, Bhi[2], Bhi[3]);
                mma16816(D[2 * p + 1], Ahi, Blo[2], Blo[3]);
                mma16816(D[2 * p + 1], Alo, Bhi[2], Bhi[3]);
            }
        }

        const float* bsm = reinterpret_cast<const float*>(smem + S3_BIAS);
        const int r0 = l >> 2, c0 = (l & 3) * 2;
#pragma unroll
        for (int half = 0; half < 2; half++) {
            int row = bt * 64 + w * 16 + half * 8 + r0;
            float* orow = out + ((size_t)row * FF + f) * EE;
#pragma unroll
            for (int nt = 0; nt < 8; nt++) {
                float2 v = make_float2(D[nt][2 * half] + bsm[nt * 8 + c0],
                                       D[nt][2 * half + 1] + bsm[nt * 8 + c0 + 1]);
                *reinterpret_cast<float2*>(orow + nt * 8 + c0) = v;
            }
        }
        __syncthreads();   // all warps done with XHI/XLO before next convert
        s ^= 1;
    }
}

extern "C" void kernel_launch(void* const* d_in, const int* in_sizes, int n_in,
                              void* d_out, int out_size) {
    const float* g     = (const float*)d_in[0];   // [B,F,F]
    const float* h     = (const float*)d_in[1];   // [B,F,E]
    const float* W_in  = (const float*)d_in[2];   // [F,E,E]
    const float* W_out = (const float*)d_in[3];   // [F,E,E]
    const float* bias  = (const float*)d_in[4];   // [E]
    float* out = (float*)d_out;                   // [B,F,E]

    __nv_bfloat16 *hohi = nullptr, *holo = nullptr;
    cudaGetSymbolAddress((void**)&hohi, g_ho_hi);
    cudaGetSymbolAddress((void**)&holo, g_ho_lo);

    cudaFuncSetAttribute((const void*)field_gemm_mma,
                         cudaFuncAttributeMaxDynamicSharedMemorySize, G_SMEM);
    cudaFuncSetAttribute((const void*)aggr_mma,
                         cudaFuncAttributeMaxDynamicSharedMemorySize, A_SMEM);
    cudaFuncSetAttribute((const void*)field3_pipe,
                         cudaFuncAttributeMaxDynamicSharedMemorySize, S3_SMEM);

    // Stage 1: ho(hi/lo) = split( einsum('fij,bfj->bfi', W_out, h) )
    field_gemm_mma<<<dim3(BB / 128, FF), 128, G_SMEM>>>(h, W_out, hohi, holo);
    // Stage 2: out = einsum('bfg,bge->bfe', g, ho)   (fp32 into d_out)
    aggr_mma<<<AGGR_GRID, 128, A_SMEM>>>(g, hohi, holo, out);
    // Stage 3 (in-place, persistent): out = einsum('fij,bfj->bfi', W_in, out) + bias
    field3_pipe<<<dim3(S3_CPF, FF), 128, S3_SMEM>>>(W_in, bias, out);
}